// round 16
// baseline (speedup 1.0000x reference)
#include <cuda_runtime.h>
#include <math.h>
#include <stdint.h>

// ---------------- scratch (device globals: allocation-free) ----------------
#define BS  4096          // B*S
#define D   1024
#define DFF 4096

__device__ float g_t1 [BS * D];
__device__ float g_o1 [BS * D];
__device__ float g_o2 [BS * D];

// split-bf16 buffers: ALL [hi|lo] 2-segment format
__device__ uint16_t g_x2  [BS * 2 * D];
__device__ uint16_t g_enc2[BS * 2 * D];
__device__ uint16_t g_o12 [BS * 2 * D];
__device__ uint16_t g_o22 [BS * 2 * D];
__device__ uint16_t g_ctx2[BS * 2 * D];
__device__ uint16_t g_ff2 [BS * 2 * DFF];
__device__ uint16_t g_q2  [BS * 2 * D];
__device__ uint16_t g_k2  [BS * 2 * D];
__device__ uint16_t g_v2  [BS * 2 * D];
__device__ uint16_t g_w2  [8][2 * D * D];
__device__ uint16_t g_wf12[2 * D * DFF];
__device__ uint16_t g_wf22[2 * DFF * D];

// ---------------- helpers ---------------------------------------------------
__device__ __forceinline__ uint32_t smem_u32(const void* p) {
    uint32_t a;
    asm("{ .reg .u64 t; cvta.to.shared.u64 t, %1; cvt.u32.u64 %0, t; }"
        : "=r"(a) : "l"(p));
    return a;
}

__device__ __forceinline__ uint32_t cvt2_bf16(float x1, float x0) {
    uint32_t r;
    asm("cvt.rn.bf16x2.f32 %0, %1, %2;" : "=r"(r) : "f"(x1), "f"(x0));
    return r;
}

__device__ __forceinline__ void split2(float x0, float x1,
                                       uint32_t& h, uint32_t& l) {
    h = cvt2_bf16(x1, x0);
    const float h0 = __uint_as_float(h << 16);
    const float h1 = __uint_as_float(h & 0xffff0000u);
    l = cvt2_bf16(x1 - h1, x0 - h0);
}

__device__ __forceinline__ void ldsm_x4(uint32_t* r, uint32_t addr) {
    asm volatile("ldmatrix.sync.aligned.m8n8.x4.shared.b16 {%0,%1,%2,%3}, [%4];"
                 : "=r"(r[0]), "=r"(r[1]), "=r"(r[2]), "=r"(r[3]) : "r"(addr));
}
__device__ __forceinline__ void ldsm_x4_t(uint32_t* r, uint32_t addr) {
    asm volatile("ldmatrix.sync.aligned.m8n8.x4.trans.shared.b16 {%0,%1,%2,%3}, [%4];"
                 : "=r"(r[0]), "=r"(r[1]), "=r"(r[2]), "=r"(r[3]) : "r"(addr));
}

__device__ __forceinline__ void mma_bf16(float* d, const uint32_t* a,
                                         const uint32_t* b) {
    asm volatile(
        "mma.sync.aligned.m16n8k16.row.col.f32.bf16.bf16.f32 "
        "{%0,%1,%2,%3}, {%4,%5,%6,%7}, {%8,%9}, {%0,%1,%2,%3};"
        : "+f"(d[0]), "+f"(d[1]), "+f"(d[2]), "+f"(d[3])
        : "r"(a[0]), "r"(a[1]), "r"(a[2]), "r"(a[3]), "r"(b[0]), "r"(b[1]));
}

__device__ __forceinline__ void cp16(uint32_t dst, const void* src) {
    asm volatile("cp.async.cg.shared.global [%0], [%1], 16;"
                 :: "r"(dst), "l"(src));
}
#define CP_COMMIT() asm volatile("cp.async.commit_group;")

// ---------------- split kernels ---------------------------------------------
struct W8 { const float* p[8]; };

// 8 attention weights D x D -> [hi;lo] B-format, one launch
__global__ void split_w8_kernel(W8 ws, uint16_t* __restrict__ out)
{
    const int wi  = blockIdx.x >> 10;                       // 1024 blocks/weight
    const int idx = ((blockIdx.x & 1023) << 8) + threadIdx.x;
    const float4 v = reinterpret_cast<const float4*>(ws.p[wi])[idx];
    uint32_t h0, l0, h1, l1;
    split2(v.x, v.y, h0, l0);
    split2(v.z, v.w, h1, l1);
    const int e = idx * 4;
    const int k = e >> 10, n = e & 1023;
    uint16_t* o = out + (size_t)wi * 2 * D * D;
    *reinterpret_cast<uint2*>(o + (size_t)k * D + n)       = make_uint2(h0, h1);
    *reinterpret_cast<uint2*>(o + (size_t)(D + k) * D + n) = make_uint2(l0, l1);
}

// both FFN weights, one launch
__global__ void split_wff_kernel(const float* __restrict__ w1,
                                 const float* __restrict__ w2i,
                                 uint16_t* __restrict__ o1,
                                 uint16_t* __restrict__ o2)
{
    const int bid = blockIdx.x;
    if (bid < 4096) {       // wff1 [D, DFF]
        const int idx = bid * 256 + threadIdx.x;
        const float4 v = reinterpret_cast<const float4*>(w1)[idx];
        uint32_t h0, l0, h1, l1;
        split2(v.x, v.y, h0, l0);
        split2(v.z, v.w, h1, l1);
        const int e = idx * 4;
        const int k = e >> 12, n = e & 4095;
        *reinterpret_cast<uint2*>(o1 + (size_t)k * DFF + n)       = make_uint2(h0, h1);
        *reinterpret_cast<uint2*>(o1 + (size_t)(D + k) * DFF + n) = make_uint2(l0, l1);
    } else {                // wff2 [DFF, D]
        const int idx = (bid - 4096) * 256 + threadIdx.x;
        const float4 v = reinterpret_cast<const float4*>(w2i)[idx];
        uint32_t h0, l0, h1, l1;
        split2(v.x, v.y, h0, l0);
        split2(v.z, v.w, h1, l1);
        const int e = idx * 4;
        const int k = e >> 10, n = e & 1023;
        *reinterpret_cast<uint2*>(o2 + (size_t)k * D + n)         = make_uint2(h0, h1);
        *reinterpret_cast<uint2*>(o2 + (size_t)(DFF + k) * D + n) = make_uint2(l0, l1);
    }
}

// x + enc activations -> [hi|lo] A-format, one launch
__global__ void split_xe_kernel(const float* __restrict__ x,
                                const float* __restrict__ enc,
                                uint16_t* __restrict__ x2,
                                uint16_t* __restrict__ e2)
{
    const int bid = blockIdx.x;
    const float* in   = (bid < 4096) ? x  : enc;
    uint16_t*    out  = (bid < 4096) ? x2 : e2;
    const int idx = ((bid & 4095) << 8) + threadIdx.x;
    const float4 v = reinterpret_cast<const float4*>(in)[idx];
    uint32_t h0, l0, h1, l1;
    split2(v.x, v.y, h0, l0);
    split2(v.z, v.w, h1, l1);
    const int e = idx * 4;
    const int m = e >> 10, k = e & 1023;
    uint16_t* rp = out + (size_t)m * 2048;
    *reinterpret_cast<uint2*>(rp + k)        = make_uint2(h0, h1);
    *reinterpret_cast<uint2*>(rp + 1024 + k) = make_uint2(l0, l1);
}

// ---------------- bf16 GEMM: virtual K'=3K over [hi|lo] operands -----------
// stage order: Ah*Bh (K), Al*Bh (K), Ah*Bl (K) via index maps.
// 128x128 CTA tile, BK=64 bf16/stage, 3-stage cp.async ring.
// OM: 0 = f32 out, 2 = split2 bf16 out [hi|lo]
#define A_STG_B 18432                     // 128 * 144
#define B_STG_B 17408                     // 64 * 272
#define STG_B   35840
#define GEMM_SMEM_BYTES (3 * STG_B)       // 107520

template <bool RELU, int OM>
__global__ __launch_bounds__(256, 2) void bf16s_gemm_kernel(
    const uint16_t* __restrict__ A2, const uint16_t* __restrict__ B2,
    const float* __restrict__ bias, void* __restrict__ Cv,
    int M, int N, int K)
{
    extern __shared__ char smem[];
    const uint32_t sb = smem_u32(smem);
    const int tid  = threadIdx.x;
    const int lane = tid & 31;
    const int wid  = tid >> 5;
    const int wm   = (wid >> 2) * 64;
    const int wn   = (wid & 3) * 32;
    const int row0 = blockIdx.y * 128;
    const int col0 = blockIdx.x * 128;
    const int K2   = 2 * K;
    const int NSK  = K >> 6;
    const int NS   = 3 * NSK;

    const int a_r = tid >> 1, a_c4 = (tid & 1) * 4;   // 128 rows, 8 slots/row
    const int b_r = tid >> 2, b_c4 = (tid & 3) * 4;   // 64 rows, 16 slots/row

    float acc[4][4][4];
    #pragma unroll
    for (int mi = 0; mi < 4; mi++)
        #pragma unroll
        for (int ni = 0; ni < 4; ni++)
            #pragma unroll
            for (int r = 0; r < 4; r++) acc[mi][ni][r] = 0.f;

    #define ISSUE_STAGE(s) do {                                               \
        const uint32_t _b = sb + ((s) % 3) * STG_B;                           \
        const int _sa = ((s) < 2 * NSK) ? (s) : (s) - 2 * NSK;                \
        const int _sb = ((s) < NSK) ? (s) : (s) - NSK;                        \
        const int _ka = _sa * 64;                                             \
        const int _kb = _sb * 64;                                             \
        _Pragma("unroll")                                                     \
        for (int p = 0; p < 4; p++) {                                         \
            cp16(_b + a_r * 144 + (a_c4 + p) * 16,                            \
                 A2 + (size_t)(row0 + a_r) * K2 + _ka + (a_c4 + p) * 8);      \
            cp16(_b + A_STG_B + b_r * 272 + (b_c4 + p) * 16,                  \
                 B2 + (size_t)(_kb + b_r) * N + col0 + (b_c4 + p) * 8);       \
        }                                                                     \
        CP_COMMIT();                                                          \
    } while (0)

    ISSUE_STAGE(0);
    ISSUE_STAGE(1);

    for (int s = 0; s < NS; s++) {
        if (s < NS - 1) asm volatile("cp.async.wait_group 1;" ::: "memory");
        else            asm volatile("cp.async.wait_group 0;" ::: "memory");
        __syncthreads();
        if (s + 2 < NS) ISSUE_STAGE(s + 2);

        const uint32_t base = sb + (s % 3) * STG_B;
        const uint32_t ab = base, bb = base + A_STG_B;

        #pragma unroll
        for (int ks = 0; ks < 4; ks++) {
            uint32_t a[4][4], bfr[2][4];
            #pragma unroll
            for (int mi = 0; mi < 4; mi++)
                ldsm_x4(a[mi], ab + (wm + (lane & 15) + mi * 16) * 144
                                  + ks * 32 + (lane >> 4) * 16);
            #pragma unroll
            for (int nj = 0; nj < 2; nj++)
                ldsm_x4_t(bfr[nj], bb + ((lane & 7) + ((lane >> 3) & 1) * 8
                                         + ks * 16) * 272
                                      + wn * 2 + (lane >> 4) * 16 + nj * 32);
            #pragma unroll
            for (int mi = 0; mi < 4; mi++)
                #pragma unroll
                for (int ni = 0; ni < 4; ni++)
                    mma_bf16(acc[mi][ni], a[mi], &bfr[ni >> 1][(ni & 1) * 2]);
        }
    }
    #undef ISSUE_STAGE

    // epilogue
    #pragma unroll
    for (int mi = 0; mi < 4; mi++) {
        const int row = row0 + wm + mi * 16 + (lane >> 2);
        #pragma unroll
        for (int ni = 0; ni < 4; ni++) {
            const int col = col0 + wn + ni * 8 + (lane & 3) * 2;
            const float b0v = bias[col], b1v = bias[col + 1];
            float v0 = acc[mi][ni][0] + b0v;
            float v1 = acc[mi][ni][1] + b1v;
            float v2 = acc[mi][ni][2] + b0v;
            float v3 = acc[mi][ni][3] + b1v;
            if (RELU) {
                v0 = fmaxf(v0, 0.f); v1 = fmaxf(v1, 0.f);
                v2 = fmaxf(v2, 0.f); v3 = fmaxf(v3, 0.f);
            }
            if (OM == 0) {
                float* C = (float*)Cv;
                *reinterpret_cast<float2*>(C + (size_t)row * N + col)
                    = make_float2(v0, v1);
                *reinterpret_cast<float2*>(C + (size_t)(row + 8) * N + col)
                    = make_float2(v2, v3);
            } else {
                uint32_t* Cw = (uint32_t*)Cv;
                uint32_t hh, ll;
                split2(v0, v1, hh, ll);
                size_t i0 = (size_t)row * N + (col >> 1);
                Cw[i0] = hh; Cw[i0 + N / 2] = ll;
                split2(v2, v3, hh, ll);
                size_t i1 = (size_t)(row + 8) * N + (col >> 1);
                Cw[i1] = hh; Cw[i1 + N / 2] = ll;
            }
        }
    }
}

// ---------------- tensor-core flash attention -------------------------------
// Q smem [64][200] bf16 [hi|lo|hi], K stage [64][200] [hi|hi|lo],
// V stage [64][136] [hi(64)|lo(64)].  2-stage cp.async ring on K/V.
// Output: ctx2 split2 bf16 [hi|lo].
#define ATT_SMEM 111616    // 25600 + 2*43008

__global__ __launch_bounds__(128) void attn_tc_kernel(
    const uint16_t* __restrict__ Q2, const uint16_t* __restrict__ K2,
    const uint16_t* __restrict__ V2, uint16_t* __restrict__ C2, int causal)
{
    extern __shared__ char smem[];
    const uint32_t sb = smem_u32(smem);
    const int tid  = threadIdx.x;
    const int lane = tid & 31;
    const int w    = tid >> 5;
    const int b    = blockIdx.x >> 4;
    const int h    = blockIdx.x & 15;
    const int q0   = blockIdx.y * 64;

    const uint32_t Qb = sb;
    const uint32_t KST0 = sb + 25600;
    const int hc = h * 64;
    const size_t qrow0 = (size_t)b * 1024 + q0;
    const int nkt = causal ? (q0 >> 6) + 1 : 16;

    #define ISSUE_TILE(j, st) do {                                            \
        const size_t _kr = (size_t)b * 1024 + (size_t)(j) * 64;               \
        const uint32_t _kb = KST0 + (st) * 43008;                             \
        for (int i = tid; i < 1536; i += 128) {                               \
            const int r = i / 24, t = i % 24, seg = t >> 3, c = t & 7;        \
            const int sc = (seg == 2 ? 1024 + hc : hc) + c * 8;               \
            cp16(_kb + r * 400 + seg * 128 + c * 16,                          \
                 K2 + (_kr + r) * 2048 + sc);                                 \
        }                                                                     \
        for (int i = tid; i < 1024; i += 128) {                               \
            const int r = i >> 4, t = i & 15, seg = t >> 3, c = t & 7;        \
            const int sc = (seg ? 1024 + hc : hc) + c * 8;                    \
            cp16(_kb + 25600 + r * 272 + seg * 128 + c * 16,                  \
                 V2 + (_kr + r) * 2048 + sc);                                 \
        }                                                                     \
        CP_COMMIT();                                                          \
    } while (0)

    for (int i = tid; i < 1536; i += 128) {
        const int r = i / 24, t = i % 24, seg = t >> 3, c = t & 7;
        const int sc = (seg == 1 ? 1024 + hc : hc) + c * 8;   // hi|lo|hi
        cp16(Qb + r * 400 + seg * 128 + c * 16, Q2 + (qrow0 + r) * 2048 + sc);
    }
    ISSUE_TILE(0, 0);
    if (nkt > 1) ISSUE_TILE(1, 1);

    float oacc[8][4];
    #pragma unroll
    for (int t = 0; t < 8; t++)
        #pragma unroll
        for (int r = 0; r < 4; r++) oacc[t][r] = 0.f;
    float m0 = -1e30f, m1 = -1e30f, l0 = 0.f, l1 = 0.f;

    const int qr0 = q0 + w * 16 + (lane >> 2);

    for (int s = 0; s < nkt; s++) {
        if (s + 1 < nkt) asm volatile("cp.async.wait_group 1;" ::: "memory");
        else             asm volatile("cp.async.wait_group 0;" ::: "memory");
        __syncthreads();
        const uint32_t Kb = KST0 + (s & 1) * 43008;
        const uint32_t Vb = Kb + 25600;

        float sc[8][4];
        #pragma unroll
        for (int t = 0; t < 8; t++)
            #pragma unroll
            for (int r = 0; r < 4; r++) sc[t][r] = 0.f;

        #pragma unroll
        for (int ks = 0; ks < 12; ks++) {
            uint32_t aq[4];
            ldsm_x4(aq, Qb + (w * 16 + (lane & 15)) * 400
                          + ks * 32 + (lane >> 4) * 16);
            #pragma unroll
            for (int nt4 = 0; nt4 < 4; nt4++) {
                uint32_t bk[4];
                ldsm_x4(bk, Kb + (nt4 * 16 + ((lane >> 4) & 1) * 8
                                  + (lane & 7)) * 400
                              + ks * 32 + ((lane >> 3) & 1) * 16);
                mma_bf16(sc[nt4 * 2], aq, &bk[0]);
                mma_bf16(sc[nt4 * 2 + 1], aq, &bk[2]);
            }
        }

        #pragma unroll
        for (int t = 0; t < 8; t++)
            #pragma unroll
            for (int r = 0; r < 4; r++) sc[t][r] *= 0.125f;

        if (causal && s == nkt - 1) {
            #pragma unroll
            for (int t = 0; t < 8; t++) {
                const int k0e = s * 64 + t * 8 + (lane & 3) * 2;
                if (k0e > qr0)         sc[t][0] = -1e30f;
                if (k0e + 1 > qr0)     sc[t][1] = -1e30f;
                if (k0e > qr0 + 8)     sc[t][2] = -1e30f;
                if (k0e + 1 > qr0 + 8) sc[t][3] = -1e30f;
            }
        }

        float mx0 = -1e30f, mx1 = -1e30f;
        #pragma unroll
        for (int t = 0; t < 8; t++) {
            mx0 = fmaxf(mx0, fmaxf(sc[t][0], sc[t][1]));
            mx1 = fmaxf(mx1, fmaxf(sc[t][2], sc[t][3]));
        }
        mx0 = fmaxf(mx0, __shfl_xor_sync(0xffffffffu, mx0, 1));
        mx0 = fmaxf(mx0, __shfl_xor_sync(0xffffffffu, mx0, 2));
        mx1 = fmaxf(mx1, __shfl_xor_sync(0xffffffffu, mx1, 1));
        mx1 = fmaxf(mx1, __shfl_xor_sync(0xffffffffu, mx1, 2));
        const float mn0 = fmaxf(m0, mx0), mn1 = fmaxf(m1, mx1);
        const float f0 = __expf(m0 - mn0), f1 = __expf(m1 - mn1);
        m0 = mn0; m1 = mn1;

        float s0 = 0.f, s1 = 0.f;
        #pragma unroll
        for (int t = 0; t < 8; t++) {
            sc[t][0] = __expf(sc[t][0] - mn0);
            sc[t][1] = __expf(sc[t][1] - mn0);
            sc[t][2] = __expf(sc[t][2] - mn1);
            sc[t][3] = __expf(sc[t][3] - mn1);
            s0 += sc[t][0] + sc[t][1];
            s1 += sc[t][2] + sc[t][3];
        }
        s0 += __shfl_xor_sync(0xffffffffu, s0, 1);
        s0 += __shfl_xor_sync(0xffffffffu, s0, 2);
        s1 += __shfl_xor_sync(0xffffffffu, s1, 1);
        s1 += __shfl_xor_sync(0xffffffffu, s1, 2);
        l0 = l0 * f0 + s0;
        l1 = l1 * f1 + s1;
        #pragma unroll
        for (int t = 0; t < 8; t++) {
            oacc[t][0] *= f0; oacc[t][1] *= f0;
            oacc[t][2] *= f1; oacc[t][3] *= f1;
        }

        #pragma unroll
        for (int ks = 0; ks < 4; ks++) {
            uint32_t ah[4], al[4];
            split2(sc[2 * ks][0],     sc[2 * ks][1],     ah[0], al[0]);
            split2(sc[2 * ks][2],     sc[2 * ks][3],     ah[1], al[1]);
            split2(sc[2 * ks + 1][0], sc[2 * ks + 1][1], ah[2], al[2]);
            split2(sc[2 * ks + 1][2], sc[2 * ks + 1][3], ah[3], al[3]);
            #pragma unroll
            for (int dt4 = 0; dt4 < 4; dt4++) {
                const uint32_t va = Vb + ((lane & 7) + ((lane >> 3) & 1) * 8
                                          + ks * 16) * 272
                                       + dt4 * 32 + (lane >> 4) * 16;
                uint32_t bh[4], bl[4];
                ldsm_x4_t(bh, va);
                ldsm_x4_t(bl, va + 128);
                mma_bf16(oacc[dt4 * 2],     ah, &bh[0]);
                mma_bf16(oacc[dt4 * 2 + 1], ah, &bh[2]);
                mma_bf16(oacc[dt4 * 2],     al, &bh[0]);
                mma_bf16(oacc[dt4 * 2 + 1], al, &bh[2]);
                mma_bf16(oacc[dt4 * 2],     ah, &bl[0]);
                mma_bf16(oacc[dt4 * 2 + 1], ah, &bl[2]);
            }
        }
        __syncthreads();
        if (s + 2 < nkt) ISSUE_TILE(s + 2, s & 1);
    }
    #undef ISSUE_TILE

    // epilogue: O/l -> ctx2 [hi|lo]
    const float i0 = 1.f / l0, i1 = 1.f / l1;
    uint32_t* Cw = (uint32_t*)C2;
    const size_t gr0 = ((size_t)b * 1024 + qr0) * 1024;    // 1024 words/row
    const size_t gr1 = gr0 + (size_t)8 * 1024;
    #pragma unroll
    for (int dt = 0; dt < 8; dt++) {
        const int cu = (hc + dt * 8 + (lane & 3) * 2) >> 1;
        uint32_t hh, ll;
        split2(oacc[dt][0] * i0, oacc[dt][1] * i0, hh, ll);
        Cw[gr0 + cu] = hh; Cw[gr0 + 512 + cu] = ll;
        split2(oacc[dt][2] * i1, oacc[dt][3] * i1, hh, ll);
        Cw[gr1 + cu] = hh; Cw[gr1 + 512 + cu] = ll;
    }
}

// ---------------- residual add + LayerNorm (+ optional split2 out) ---------
__device__ __forceinline__ float block_sum_256(float v, float* red)
{
    #pragma unroll
    for (int o = 16; o > 0; o >>= 1) v += __shfl_xor_sync(0xffffffffu, v, o);
    const int w = threadIdx.x >> 5;
    if ((threadIdx.x & 31) == 0) red[w] = v;
    __syncthreads();
    v = red[threadIdx.x & 7];
    #pragma unroll
    for (int o = 4; o > 0; o >>= 1) v += __shfl_xor_sync(0xffffffffu, v, o);
    __syncthreads();
    return v;
}

__global__ __launch_bounds__(256) void ln_kernel(
    const float* __restrict__ X, const float* __restrict__ Y,
    const float* __restrict__ g, const float* __restrict__ be,
    float* __restrict__ out, uint16_t* __restrict__ out2)
{
    __shared__ float sm[D];
    __shared__ float red[8];
    const int row = blockIdx.x;
    const int tid = threadIdx.x;
    const float* x = X + (size_t)row * D;
    const float* y = Y + (size_t)row * D;

    float local = 0.f;
    #pragma unroll
    for (int i = tid; i < D; i += 256) {
        const float v = x[i] + y[i];
        sm[i] = v;
        local += v;
    }
    const float mean = block_sum_256(local, red) * (1.f / D);

    float lv = 0.f;
    #pragma unroll
    for (int i = tid; i < D; i += 256) {
        const float d = sm[i] - mean;
        lv += d * d;
    }
    const float var = block_sum_256(lv, red) * (1.f / D);
    const float rstd = rsqrtf(var + 1e-3f);

    if (out2) {
        uint16_t* r2 = out2 + (size_t)row * 2 * D;
        #pragma unroll
        for (int i = tid; i < D; i += 256) {
            const float val = (sm[i] - mean) * rstd * g[i] + be[i];
            out[(size_t)row * D + i] = val;
            uint32_t hh, ll;
            split2(val, 0.f, hh, ll);
            r2[i]     = (uint16_t)hh;
            r2[D + i] = (uint16_t)ll;
        }
    } else {
        #pragma unroll
        for (int i = tid; i < D; i += 256)
            out[(size_t)row * D + i] = (sm[i] - mean) * rstd * g[i] + be[i];
    }
}

// ---------------- host orchestration ---------------------------------------
extern "C" void kernel_launch(void* const* d_in, const int* in_sizes, int n_in,
                              void* d_out, int out_size)
{
    const float* x   = (const float*)d_in[0];
    const float* enc = (const float*)d_in[1];

    const float *wq1, *bq1, *wk1, *bk1, *wv1, *bv1, *wo1, *bo1;
    const float *wq2, *bq2, *wk2, *bk2, *wv2, *bv2, *wo2, *bo2;
    const float *wff1, *bff1, *wff2, *bff2;
    const float *g1, *be1, *g2, *be2, *g3, *be3;

    if (in_sizes[3] == 1024) {
        wq1 = (const float*)d_in[2];  bq1 = (const float*)d_in[3];
        wk1 = (const float*)d_in[4];  bk1 = (const float*)d_in[5];
        wv1 = (const float*)d_in[6];  bv1 = (const float*)d_in[7];
        wo1 = (const float*)d_in[8];  bo1 = (const float*)d_in[9];
        wq2 = (const float*)d_in[10]; bq2 = (const float*)d_in[11];
        wk2 = (const float*)d_in[12]; bk2 = (const float*)d_in[13];
        wv2 = (const float*)d_in[14]; bv2 = (const float*)d_in[15];
        wo2 = (const float*)d_in[16]; bo2 = (const float*)d_in[17];
    } else {
        wq1 = (const float*)d_in[2];  wk1 = (const float*)d_in[3];
        wv1 = (const float*)d_in[4];  wo1 = (const float*)d_in[5];
        bq1 = (const float*)d_in[6];  bk1 = (const float*)d_in[7];
        bv1 = (const float*)d_in[8];  bo1 = (const float*)d_in[9];
        wq2 = (const float*)d_in[10]; wk2 = (const float*)d_in[11];
        wv2 = (const float*)d_in[12]; wo2 = (const float*)d_in[13];
        bq2 = (const float*)d_in[14]; bk2 = (const float*)d_in[15];
        bv2 = (const float*)d_in[16]; bo2 = (const float*)d_in[17];
    }
    wff1 = (const float*)d_in[18]; bff1 = (const float*)d_in[19];
    wff2 = (const float*)d_in[20]; bff2 = (const float*)d_in[21];
    g1 = (const float*)d_in[22]; be1 = (const float*)d_in[23];
    g2 = (const float*)d_in[24]; be2 = (const float*)d_in[25];
    g3 = (const float*)d_in[26]; be3 = (const float*)d_in[27];

    float *t1, *o1, *o2;
    cudaGetSymbolAddress((void**)&t1, g_t1);
    cudaGetSymbolAddress((void**)&o1, g_o1);
    cudaGetSymbolAddress((void**)&o2, g_o2);

    uint16_t *x2, *enc2, *o12, *o22, *ctx2, *ff2, *q2, *k2, *v2;
    uint16_t *w2, *wf12, *wf22;
    cudaGetSymbolAddress((void**)&x2,   g_x2);
    cudaGetSymbolAddress((void**)&enc2, g_enc2);
    cudaGetSymbolAddress((void**)&o12,  g_o12);
    cudaGetSymbolAddress((void**)&o22,  g_o22);
    cudaGetSymbolAddress((void**)&ctx2, g_ctx2);
    cudaGetSymbolAddress((void**)&ff2,  g_ff2);
    cudaGetSymbolAddress((void**)&q2,   g_q2);
    cudaGetSymbolAddress((void**)&k2,   g_k2);
    cudaGetSymbolAddress((void**)&v2,   g_v2);
    cudaGetSymbolAddress((void**)&w2,   g_w2);
    cudaGetSymbolAddress((void**)&wf12, g_wf12);
    cudaGetSymbolAddress((void**)&wf22, g_wf22);

    cudaFuncSetAttribute(bf16s_gemm_kernel<false, 0>,
        cudaFuncAttributeMaxDynamicSharedMemorySize, GEMM_SMEM_BYTES);
    cudaFuncSetAttribute(bf16s_gemm_kernel<false, 2>,
        cudaFuncAttributeMaxDynamicSharedMemorySize, GEMM_SMEM_BYTES);
    cudaFuncSetAttribute(bf16s_gemm_kernel<true, 2>,
        cudaFuncAttributeMaxDynamicSharedMemorySize, GEMM_SMEM_BYTES);
    cudaFuncSetAttribute(attn_tc_kernel,
        cudaFuncAttributeMaxDynamicSharedMemorySize, ATT_SMEM);

    const dim3 gD(D / 128, BS / 128);
    const dim3 gF1(DFF / 128, BS / 128);
    const dim3 gAttn(64, 16);
    const int SM = GEMM_SMEM_BYTES;
    const size_t WSZ = (size_t)2 * D * D;

    // splits: 3 launches total
    W8 w8s;
    w8s.p[0] = wq1; w8s.p[1] = wk1; w8s.p[2] = wv1; w8s.p[3] = wo1;
    w8s.p[4] = wq2; w8s.p[5] = wk2; w8s.p[6] = wv2; w8s.p[7] = wo2;
    split_w8_kernel<<<8192, 256>>>(w8s, w2);
    split_wff_kernel<<<8192, 256>>>(wff1, wff2, wf12, wf22);
    split_xe_kernel<<<8192, 256>>>(x, enc, x2, enc2);

    // ---- self-attention block (causal) ----
    bf16s_gemm_kernel<false, 2><<<gD, 256, SM>>>(x2, w2 + 0 * WSZ, bq1, q2, BS, D, D);
    bf16s_gemm_kernel<false, 2><<<gD, 256, SM>>>(x2, w2 + 1 * WSZ, bk1, k2, BS, D, D);
    bf16s_gemm_kernel<false, 2><<<gD, 256, SM>>>(x2, w2 + 2 * WSZ, bv1, v2, BS, D, D);
    attn_tc_kernel<<<gAttn, 128, ATT_SMEM>>>(q2, k2, v2, ctx2, 1);
    bf16s_gemm_kernel<false, 0><<<gD, 256, SM>>>(ctx2, w2 + 3 * WSZ, bo1, t1, BS, D, D);
    ln_kernel<<<BS, 256>>>(x, t1, g1, be1, o1, o12);

    // ---- cross-attention block ----
    bf16s_gemm_kernel<false, 2><<<gD, 256, SM>>>(o12,  w2 + 4 * WSZ, bq2, q2, BS, D, D);
    bf16s_gemm_kernel<false, 2><<<gD, 256, SM>>>(enc2, w2 + 5 * WSZ, bk2, k2, BS, D, D);
    bf16s_gemm_kernel<false, 2><<<gD, 256, SM>>>(enc2, w2 + 6 * WSZ, bv2, v2, BS, D, D);
    attn_tc_kernel<<<gAttn, 128, ATT_SMEM>>>(q2, k2, v2, ctx2, 0);
    bf16s_gemm_kernel<false, 0><<<gD, 256, SM>>>(ctx2, w2 + 7 * WSZ, bo2, t1, BS, D, D);
    ln_kernel<<<BS, 256>>>(o1, t1, g2, be2, o2, o22);

    // ---- FFN block ----
    bf16s_gemm_kernel<true, 2><<<gF1, 256, SM>>>(o22, wf12, bff1, ff2, BS, DFF, D);
    bf16s_gemm_kernel<false, 0><<<gD, 256, SM>>>(ff2, wf22, bff2, t1, BS, D, DFF);
    ln_kernel<<<BS, 256>>>(o2, t1, g3, be3, (float*)d_out, nullptr);

    (void)n_in; (void)out_size;
}

// round 17
// speedup vs baseline: 1.2189x; 1.2189x over previous
#include <cuda_runtime.h>
#include <math.h>
#include <stdint.h>

// ---------------- scratch (device globals: allocation-free) ----------------
#define BS  4096          // B*S
#define D   1024
#define DFF 4096

__device__ float g_t1 [BS * D];
__device__ float g_o1 [BS * D];
__device__ float g_o2 [BS * D];

// split-bf16 buffers
__device__ uint16_t g_x3  [BS * 3 * D];     // [hi|lo|hi] A-format
__device__ uint16_t g_enc3[BS * 3 * D];
__device__ uint16_t g_o13 [BS * 3 * D];
__device__ uint16_t g_o23 [BS * 3 * D];
__device__ uint16_t g_ctx3[BS * 3 * D];
__device__ uint16_t g_ff3 [BS * 3 * DFF];
__device__ uint16_t g_q2  [BS * 2 * D];     // [hi|lo]
__device__ uint16_t g_k2  [BS * 2 * D];
__device__ uint16_t g_v2  [BS * 2 * D];
__device__ uint16_t g_w3  [8][3 * D * D];   // [hi;hi;lo] B-format
__device__ uint16_t g_wf13[3 * D * DFF];
__device__ uint16_t g_wf23[3 * DFF * D];

// ---------------- helpers ---------------------------------------------------
__device__ __forceinline__ uint32_t smem_u32(const void* p) {
    uint32_t a;
    asm("{ .reg .u64 t; cvta.to.shared.u64 t, %1; cvt.u32.u64 %0, t; }"
        : "=r"(a) : "l"(p));
    return a;
}

__device__ __forceinline__ uint32_t cvt2_bf16(float x1, float x0) {
    uint32_t r;
    asm("cvt.rn.bf16x2.f32 %0, %1, %2;" : "=r"(r) : "f"(x1), "f"(x0));
    return r;
}

__device__ __forceinline__ void split2(float x0, float x1,
                                       uint32_t& h, uint32_t& l) {
    h = cvt2_bf16(x1, x0);
    const float h0 = __uint_as_float(h << 16);
    const float h1 = __uint_as_float(h & 0xffff0000u);
    l = cvt2_bf16(x1 - h1, x0 - h0);
}

__device__ __forceinline__ void ldsm_x4(uint32_t* r, uint32_t addr) {
    asm volatile("ldmatrix.sync.aligned.m8n8.x4.shared.b16 {%0,%1,%2,%3}, [%4];"
                 : "=r"(r[0]), "=r"(r[1]), "=r"(r[2]), "=r"(r[3]) : "r"(addr));
}
__device__ __forceinline__ void ldsm_x4_t(uint32_t* r, uint32_t addr) {
    asm volatile("ldmatrix.sync.aligned.m8n8.x4.trans.shared.b16 {%0,%1,%2,%3}, [%4];"
                 : "=r"(r[0]), "=r"(r[1]), "=r"(r[2]), "=r"(r[3]) : "r"(addr));
}

__device__ __forceinline__ void mma_bf16(float* d, const uint32_t* a,
                                         const uint32_t* b) {
    asm volatile(
        "mma.sync.aligned.m16n8k16.row.col.f32.bf16.bf16.f32 "
        "{%0,%1,%2,%3}, {%4,%5,%6,%7}, {%8,%9}, {%0,%1,%2,%3};"
        : "+f"(d[0]), "+f"(d[1]), "+f"(d[2]), "+f"(d[3])
        : "r"(a[0]), "r"(a[1]), "r"(a[2]), "r"(a[3]), "r"(b[0]), "r"(b[1]));
}

__device__ __forceinline__ void cp16(uint32_t dst, const void* src) {
    asm volatile("cp.async.cg.shared.global [%0], [%1], 16;"
                 :: "r"(dst), "l"(src));
}
#define CP_COMMIT() asm volatile("cp.async.commit_group;")

// ---------------- split kernels (3 launches total) --------------------------
struct W8 { const float* p[8]; };

// 8 attention weights D x D -> 3-seg B-format [hi;hi;lo]
__global__ void split_w8_kernel(W8 ws, uint16_t* __restrict__ out)
{
    const int wi  = blockIdx.x >> 10;
    const int idx = ((blockIdx.x & 1023) << 8) + threadIdx.x;
    const float4 v = reinterpret_cast<const float4*>(ws.p[wi])[idx];
    uint32_t h0, l0, h1, l1;
    split2(v.x, v.y, h0, l0);
    split2(v.z, v.w, h1, l1);
    const int e = idx * 4;
    const int k = e >> 10, n = e & 1023;
    uint16_t* o = out + (size_t)wi * 3 * D * D;
    const uint2 H = make_uint2(h0, h1), L = make_uint2(l0, l1);
    *reinterpret_cast<uint2*>(o + (size_t)k * D + n)           = H;
    *reinterpret_cast<uint2*>(o + (size_t)(D + k) * D + n)     = H;
    *reinterpret_cast<uint2*>(o + (size_t)(2 * D + k) * D + n) = L;
}

// both FFN weights -> 3-seg B-format, one launch
__global__ void split_wff_kernel(const float* __restrict__ w1,
                                 const float* __restrict__ w2i,
                                 uint16_t* __restrict__ o1,
                                 uint16_t* __restrict__ o2)
{
    const int bid = blockIdx.x;
    if (bid < 4096) {       // wff1 [D, DFF]
        const int idx = bid * 256 + threadIdx.x;
        const float4 v = reinterpret_cast<const float4*>(w1)[idx];
        uint32_t h0, l0, h1, l1;
        split2(v.x, v.y, h0, l0);
        split2(v.z, v.w, h1, l1);
        const int e = idx * 4;
        const int k = e >> 12, n = e & 4095;
        const uint2 H = make_uint2(h0, h1), L = make_uint2(l0, l1);
        *reinterpret_cast<uint2*>(o1 + (size_t)k * DFF + n)           = H;
        *reinterpret_cast<uint2*>(o1 + (size_t)(D + k) * DFF + n)     = H;
        *reinterpret_cast<uint2*>(o1 + (size_t)(2 * D + k) * DFF + n) = L;
    } else {                // wff2 [DFF, D]
        const int idx = (bid - 4096) * 256 + threadIdx.x;
        const float4 v = reinterpret_cast<const float4*>(w2i)[idx];
        uint32_t h0, l0, h1, l1;
        split2(v.x, v.y, h0, l0);
        split2(v.z, v.w, h1, l1);
        const int e = idx * 4;
        const int k = e >> 10, n = e & 1023;
        const uint2 H = make_uint2(h0, h1), L = make_uint2(l0, l1);
        *reinterpret_cast<uint2*>(o2 + (size_t)k * D + n)             = H;
        *reinterpret_cast<uint2*>(o2 + (size_t)(DFF + k) * D + n)     = H;
        *reinterpret_cast<uint2*>(o2 + (size_t)(2 * DFF + k) * D + n) = L;
    }
}

// x + enc activations -> 3-seg A-format [hi|lo|hi], one launch
__global__ void split_xe_kernel(const float* __restrict__ x,
                                const float* __restrict__ enc,
                                uint16_t* __restrict__ x3,
                                uint16_t* __restrict__ e3)
{
    const int bid = blockIdx.x;
    const float* in  = (bid < 4096) ? x  : enc;
    uint16_t*    out = (bid < 4096) ? x3 : e3;
    const int idx = ((bid & 4095) << 8) + threadIdx.x;
    const float4 v = reinterpret_cast<const float4*>(in)[idx];
    uint32_t h0, l0, h1, l1;
    split2(v.x, v.y, h0, l0);
    split2(v.z, v.w, h1, l1);
    const int e = idx * 4;
    const int m = e >> 10, k = e & 1023;
    uint16_t* rp = out + (size_t)m * 3 * D;
    const uint2 H = make_uint2(h0, h1), L = make_uint2(l0, l1);
    *reinterpret_cast<uint2*>(rp + k)           = H;
    *reinterpret_cast<uint2*>(rp + D + k)       = L;
    *reinterpret_cast<uint2*>(rp + 2 * D + k)   = H;
}

// ---------------- bf16 GEMM: C = A'[M,K3] @ B'[K3,N] + bias (+ReLU) --------
// 128x128 CTA tile, BK=32 bf16, cp.async 4-stage ring (3-ahead prefetch).
// OM: 0 = f32 out, 2 = split2 bf16 [hi|lo], 3 = split3 bf16 [hi|lo|hi]
#define A_STG_B 10240                     // 128 * 80
#define B_STG_B 8704                      // 32 * 272
#define STG_B   (A_STG_B + B_STG_B)       // 18944
#define GEMM_SMEM_BYTES (4 * STG_B)       // 75776

template <bool RELU, int OM>
__global__ __launch_bounds__(256, 2) void bf16s_gemm_kernel(
    const uint16_t* __restrict__ A3, const uint16_t* __restrict__ B3,
    const float* __restrict__ bias, void* __restrict__ Cv,
    int M, int N, int K3)
{
    extern __shared__ char smem[];
    const uint32_t sb = smem_u32(smem);
    const int tid  = threadIdx.x;
    const int lane = tid & 31;
    const int wid  = tid >> 5;
    const int wm   = (wid >> 2) * 64;
    const int wn   = (wid & 3) * 32;
    const int row0 = blockIdx.y * 128;
    const int col0 = blockIdx.x * 128;
    const int NS   = K3 >> 5;

    const int a_r  = tid >> 2, a_sg = tid & 3;
    const int b_r  = tid >> 4, b_sg = tid & 15;

    float acc[4][4][4];
    #pragma unroll
    for (int mi = 0; mi < 4; mi++)
        #pragma unroll
        for (int ni = 0; ni < 4; ni++)
            #pragma unroll
            for (int r = 0; r < 4; r++) acc[mi][ni][r] = 0.f;

    #define ISSUE_STAGE(s) do {                                               \
        const uint32_t _b = sb + ((s) & 3) * STG_B;                           \
        const int _k0 = (s) * 32;                                             \
        cp16(_b + a_r * 80 + a_sg * 16,                                       \
             A3 + (size_t)(row0 + a_r) * K3 + _k0 + a_sg * 8);                \
        cp16(_b + (a_r + 64) * 80 + a_sg * 16,                                \
             A3 + (size_t)(row0 + a_r + 64) * K3 + _k0 + a_sg * 8);           \
        cp16(_b + A_STG_B + b_r * 272 + b_sg * 16,                            \
             B3 + (size_t)(_k0 + b_r) * N + col0 + b_sg * 8);                 \
        cp16(_b + A_STG_B + (b_r + 16) * 272 + b_sg * 16,                     \
             B3 + (size_t)(_k0 + b_r + 16) * N + col0 + b_sg * 8);            \
        CP_COMMIT();                                                          \
    } while (0)

    ISSUE_STAGE(0);
    ISSUE_STAGE(1);
    ISSUE_STAGE(2);

    for (int s = 0; s < NS; s++) {
        if (s + 3 <= NS)      asm volatile("cp.async.wait_group 2;" ::: "memory");
        else if (s + 2 == NS) asm volatile("cp.async.wait_group 1;" ::: "memory");
        else                  asm volatile("cp.async.wait_group 0;" ::: "memory");
        __syncthreads();
        if (s + 3 < NS) ISSUE_STAGE(s + 3);

        const uint32_t base = sb + (s & 3) * STG_B;
        const uint32_t ab = base, bb = base + A_STG_B;

        #pragma unroll
        for (int ks = 0; ks < 2; ks++) {
            uint32_t a[4][4], bfr[2][4];
            #pragma unroll
            for (int mi = 0; mi < 4; mi++)
                ldsm_x4(a[mi], ab + (wm + (lane & 15) + mi * 16) * 80
                                  + ks * 32 + (lane >> 4) * 16);
            #pragma unroll
            for (int nj = 0; nj < 2; nj++)
                ldsm_x4_t(bfr[nj], bb + ((lane & 7) + ((lane >> 3) & 1) * 8
                                         + ks * 16) * 272
                                      + wn * 2 + (lane >> 4) * 16 + nj * 32);
            #pragma unroll
            for (int mi = 0; mi < 4; mi++)
                #pragma unroll
                for (int ni = 0; ni < 4; ni++)
                    mma_bf16(acc[mi][ni], a[mi], &bfr[ni >> 1][(ni & 1) * 2]);
        }
    }
    #undef ISSUE_STAGE

    // epilogue
    #pragma unroll
    for (int mi = 0; mi < 4; mi++) {
        const int row = row0 + wm + mi * 16 + (lane >> 2);
        #pragma unroll
        for (int ni = 0; ni < 4; ni++) {
            const int col = col0 + wn + ni * 8 + (lane & 3) * 2;
            const float b0v = bias[col], b1v = bias[col + 1];
            float v0 = acc[mi][ni][0] + b0v;
            float v1 = acc[mi][ni][1] + b1v;
            float v2 = acc[mi][ni][2] + b0v;
            float v3 = acc[mi][ni][3] + b1v;
            if (RELU) {
                v0 = fmaxf(v0, 0.f); v1 = fmaxf(v1, 0.f);
                v2 = fmaxf(v2, 0.f); v3 = fmaxf(v3, 0.f);
            }
            if (OM == 0) {
                float* C = (float*)Cv;
                *reinterpret_cast<float2*>(C + (size_t)row * N + col)
                    = make_float2(v0, v1);
                *reinterpret_cast<float2*>(C + (size_t)(row + 8) * N + col)
                    = make_float2(v2, v3);
            } else {
                uint32_t* Cw = (uint32_t*)Cv;
                const int p32 = (OM == 2) ? N : (3 * N) / 2;
                uint32_t hh, ll;
                split2(v0, v1, hh, ll);
                size_t i0 = (size_t)row * p32 + (col >> 1);
                Cw[i0] = hh; Cw[i0 + N / 2] = ll;
                if (OM == 3) Cw[i0 + N] = hh;
                split2(v2, v3, hh, ll);
                size_t i1 = (size_t)(row + 8) * p32 + (col >> 1);
                Cw[i1] = hh; Cw[i1 + N / 2] = ll;
                if (OM == 3) Cw[i1 + N] = hh;
            }
        }
    }
}

// ---------------- tensor-core flash attention -------------------------------
// Q smem [64][200] bf16 [hi|lo|hi], K stage [64][200] [hi|hi|lo],
// V stage [64][136] [hi(64)|lo(64)].  2-stage cp.async ring on K/V.
// Output: ctx3 split3 bf16 [hi|lo|hi].
#define ATT_SMEM 111616    // 25600 + 2*43008

__global__ __launch_bounds__(128) void attn_tc_kernel(
    const uint16_t* __restrict__ Q2, const uint16_t* __restrict__ K2,
    const uint16_t* __restrict__ V2, uint16_t* __restrict__ C3, int causal)
{
    extern __shared__ char smem[];
    const uint32_t sb = smem_u32(smem);
    const int tid  = threadIdx.x;
    const int lane = tid & 31;
    const int w    = tid >> 5;
    const int b    = blockIdx.x >> 4;
    const int h    = blockIdx.x & 15;
    const int q0   = blockIdx.y * 64;

    const uint32_t Qb = sb;
    const uint32_t KST0 = sb + 25600;
    const int hc = h * 64;
    const size_t qrow0 = (size_t)b * 1024 + q0;
    const int nkt = causal ? (q0 >> 6) + 1 : 16;

    #define ISSUE_TILE(j, st) do {                                            \
        const size_t _kr = (size_t)b * 1024 + (size_t)(j) * 64;               \
        const uint32_t _kb = KST0 + (st) * 43008;                             \
        for (int i = tid; i < 1536; i += 128) {                               \
            const int r = i / 24, t = i % 24, seg = t >> 3, c = t & 7;        \
            const int sc = (seg == 2 ? 1024 + hc : hc) + c * 8;               \
            cp16(_kb + r * 400 + seg * 128 + c * 16,                          \
                 K2 + (_kr + r) * 2048 + sc);                                 \
        }                                                                     \
        for (int i = tid; i < 1024; i += 128) {                               \
            const int r = i >> 4, t = i & 15, seg = t >> 3, c = t & 7;        \
            const int sc = (seg ? 1024 + hc : hc) + c * 8;                    \
            cp16(_kb + 25600 + r * 272 + seg * 128 + c * 16,                  \
                 V2 + (_kr + r) * 2048 + sc);                                 \
        }                                                                     \
        CP_COMMIT();                                                          \
    } while (0)

    for (int i = tid; i < 1536; i += 128) {
        const int r = i / 24, t = i % 24, seg = t >> 3, c = t & 7;
        const int sc = (seg == 1 ? 1024 + hc : hc) + c * 8;   // hi|lo|hi
        cp16(Qb + r * 400 + seg * 128 + c * 16, Q2 + (qrow0 + r) * 2048 + sc);
    }
    ISSUE_TILE(0, 0);
    if (nkt > 1) ISSUE_TILE(1, 1);

    float oacc[8][4];
    #pragma unroll
    for (int t = 0; t < 8; t++)
        #pragma unroll
        for (int r = 0; r < 4; r++) oacc[t][r] = 0.f;
    float m0 = -1e30f, m1 = -1e30f, l0 = 0.f, l1 = 0.f;

    const int qr0 = q0 + w * 16 + (lane >> 2);

    for (int s = 0; s < nkt; s++) {
        if (s + 1 < nkt) asm volatile("cp.async.wait_group 1;" ::: "memory");
        else             asm volatile("cp.async.wait_group 0;" ::: "memory");
        __syncthreads();
        const uint32_t Kb = KST0 + (s & 1) * 43008;
        const uint32_t Vb = Kb + 25600;

        float sc[8][4];
        #pragma unroll
        for (int t = 0; t < 8; t++)
            #pragma unroll
            for (int r = 0; r < 4; r++) sc[t][r] = 0.f;

        #pragma unroll
        for (int ks = 0; ks < 12; ks++) {
            uint32_t aq[4];
            ldsm_x4(aq, Qb + (w * 16 + (lane & 15)) * 400
                          + ks * 32 + (lane >> 4) * 16);
            #pragma unroll
            for (int nt4 = 0; nt4 < 4; nt4++) {
                uint32_t bk[4];
                ldsm_x4(bk, Kb + (nt4 * 16 + ((lane >> 4) & 1) * 8
                                  + (lane & 7)) * 400
                              + ks * 32 + ((lane >> 3) & 1) * 16);
                mma_bf16(sc[nt4 * 2], aq, &bk[0]);
                mma_bf16(sc[nt4 * 2 + 1], aq, &bk[2]);
            }
        }

        #pragma unroll
        for (int t = 0; t < 8; t++)
            #pragma unroll
            for (int r = 0; r < 4; r++) sc[t][r] *= 0.125f;

        if (causal && s == nkt - 1) {
            #pragma unroll
            for (int t = 0; t < 8; t++) {
                const int k0e = s * 64 + t * 8 + (lane & 3) * 2;
                if (k0e > qr0)         sc[t][0] = -1e30f;
                if (k0e + 1 > qr0)     sc[t][1] = -1e30f;
                if (k0e > qr0 + 8)     sc[t][2] = -1e30f;
                if (k0e + 1 > qr0 + 8) sc[t][3] = -1e30f;
            }
        }

        float mx0 = -1e30f, mx1 = -1e30f;
        #pragma unroll
        for (int t = 0; t < 8; t++) {
            mx0 = fmaxf(mx0, fmaxf(sc[t][0], sc[t][1]));
            mx1 = fmaxf(mx1, fmaxf(sc[t][2], sc[t][3]));
        }
        mx0 = fmaxf(mx0, __shfl_xor_sync(0xffffffffu, mx0, 1));
        mx0 = fmaxf(mx0, __shfl_xor_sync(0xffffffffu, mx0, 2));
        mx1 = fmaxf(mx1, __shfl_xor_sync(0xffffffffu, mx1, 1));
        mx1 = fmaxf(mx1, __shfl_xor_sync(0xffffffffu, mx1, 2));
        const float mn0 = fmaxf(m0, mx0), mn1 = fmaxf(m1, mx1);
        const float f0 = __expf(m0 - mn0), f1 = __expf(m1 - mn1);
        m0 = mn0; m1 = mn1;

        float s0 = 0.f, s1 = 0.f;
        #pragma unroll
        for (int t = 0; t < 8; t++) {
            sc[t][0] = __expf(sc[t][0] - mn0);
            sc[t][1] = __expf(sc[t][1] - mn0);
            sc[t][2] = __expf(sc[t][2] - mn1);
            sc[t][3] = __expf(sc[t][3] - mn1);
            s0 += sc[t][0] + sc[t][1];
            s1 += sc[t][2] + sc[t][3];
        }
        s0 += __shfl_xor_sync(0xffffffffu, s0, 1);
        s0 += __shfl_xor_sync(0xffffffffu, s0, 2);
        s1 += __shfl_xor_sync(0xffffffffu, s1, 1);
        s1 += __shfl_xor_sync(0xffffffffu, s1, 2);
        l0 = l0 * f0 + s0;
        l1 = l1 * f1 + s1;
        #pragma unroll
        for (int t = 0; t < 8; t++) {
            oacc[t][0] *= f0; oacc[t][1] *= f0;
            oacc[t][2] *= f1; oacc[t][3] *= f1;
        }

        #pragma unroll
        for (int ks = 0; ks < 4; ks++) {
            uint32_t ah[4], al[4];
            split2(sc[2 * ks][0],     sc[2 * ks][1],     ah[0], al[0]);
            split2(sc[2 * ks][2],     sc[2 * ks][3],     ah[1], al[1]);
            split2(sc[2 * ks + 1][0], sc[2 * ks + 1][1], ah[2], al[2]);
            split2(sc[2 * ks + 1][2], sc[2 * ks + 1][3], ah[3], al[3]);
            #pragma unroll
            for (int dt4 = 0; dt4 < 4; dt4++) {
                const uint32_t va = Vb + ((lane & 7) + ((lane >> 3) & 1) * 8
                                          + ks * 16) * 272
                                       + dt4 * 32 + (lane >> 4) * 16;
                uint32_t bh[4], bl[4];
                ldsm_x4_t(bh, va);
                ldsm_x4_t(bl, va + 128);
                mma_bf16(oacc[dt4 * 2],     ah, &bh[0]);
                mma_bf16(oacc[dt4 * 2 + 1], ah, &bh[2]);
                mma_bf16(oacc[dt4 * 2],     al, &bh[0]);
                mma_bf16(oacc[dt4 * 2 + 1], al, &bh[2]);
                mma_bf16(oacc[dt4 * 2],     ah, &bl[0]);
                mma_bf16(oacc[dt4 * 2 + 1], ah, &bl[2]);
            }
        }
        __syncthreads();
        if (s + 2 < nkt) ISSUE_TILE(s + 2, s & 1);
    }
    #undef ISSUE_TILE

    // epilogue: O/l -> ctx3 split3 [hi|lo|hi]
    const float i0 = 1.f / l0, i1 = 1.f / l1;
    uint32_t* Cw = (uint32_t*)C3;
    const size_t gr0 = ((size_t)b * 1024 + qr0) * 1536;
    const size_t gr1 = gr0 + (size_t)8 * 1536;
    #pragma unroll
    for (int dt = 0; dt < 8; dt++) {
        const int cu = (hc + dt * 8 + (lane & 3) * 2) >> 1;
        uint32_t hh, ll;
        split2(oacc[dt][0] * i0, oacc[dt][1] * i0, hh, ll);
        Cw[gr0 + cu] = hh; Cw[gr0 + 512 + cu] = ll; Cw[gr0 + 1024 + cu] = hh;
        split2(oacc[dt][2] * i1, oacc[dt][3] * i1, hh, ll);
        Cw[gr1 + cu] = hh; Cw[gr1 + 512 + cu] = ll; Cw[gr1 + 1024 + cu] = hh;
    }
}

// ---------------- residual add + LayerNorm (+ optional split3 out) ---------
__device__ __forceinline__ float block_sum_256(float v, float* red)
{
    #pragma unroll
    for (int o = 16; o > 0; o >>= 1) v += __shfl_xor_sync(0xffffffffu, v, o);
    const int w = threadIdx.x >> 5;
    if ((threadIdx.x & 31) == 0) red[w] = v;
    __syncthreads();
    v = red[threadIdx.x & 7];
    #pragma unroll
    for (int o = 4; o > 0; o >>= 1) v += __shfl_xor_sync(0xffffffffu, v, o);
    __syncthreads();
    return v;
}

__global__ __launch_bounds__(256) void ln_kernel(
    const float* __restrict__ X, const float* __restrict__ Y,
    const float* __restrict__ g, const float* __restrict__ be,
    float* __restrict__ out, uint16_t* __restrict__ out3)
{
    __shared__ float sm[D];
    __shared__ float red[8];
    const int row = blockIdx.x;
    const int tid = threadIdx.x;
    const float* x = X + (size_t)row * D;
    const float* y = Y + (size_t)row * D;

    float local = 0.f;
    #pragma unroll
    for (int i = tid; i < D; i += 256) {
        const float v = x[i] + y[i];
        sm[i] = v;
        local += v;
    }
    const float mean = block_sum_256(local, red) * (1.f / D);

    float lv = 0.f;
    #pragma unroll
    for (int i = tid; i < D; i += 256) {
        const float d = sm[i] - mean;
        lv += d * d;
    }
    const float var = block_sum_256(lv, red) * (1.f / D);
    const float rstd = rsqrtf(var + 1e-3f);

    if (out3) {
        uint16_t* r3 = out3 + (size_t)row * 3 * D;
        #pragma unroll
        for (int i = tid; i < D; i += 256) {
            const float val = (sm[i] - mean) * rstd * g[i] + be[i];
            out[(size_t)row * D + i] = val;
            uint32_t hh, ll;
            split2(val, 0.f, hh, ll);
            r3[i]         = (uint16_t)hh;
            r3[D + i]     = (uint16_t)ll;
            r3[2 * D + i] = (uint16_t)hh;
        }
    } else {
        #pragma unroll
        for (int i = tid; i < D; i += 256)
            out[(size_t)row * D + i] = (sm[i] - mean) * rstd * g[i] + be[i];
    }
}

// ---------------- host orchestration ---------------------------------------
extern "C" void kernel_launch(void* const* d_in, const int* in_sizes, int n_in,
                              void* d_out, int out_size)
{
    const float* x   = (const float*)d_in[0];
    const float* enc = (const float*)d_in[1];

    const float *wq1, *bq1, *wk1, *bk1, *wv1, *bv1, *wo1, *bo1;
    const float *wq2, *bq2, *wk2, *bk2, *wv2, *bv2, *wo2, *bo2;
    const float *wff1, *bff1, *wff2, *bff2;
    const float *g1, *be1, *g2, *be2, *g3, *be3;

    if (in_sizes[3] == 1024) {
        wq1 = (const float*)d_in[2];  bq1 = (const float*)d_in[3];
        wk1 = (const float*)d_in[4];  bk1 = (const float*)d_in[5];
        wv1 = (const float*)d_in[6];  bv1 = (const float*)d_in[7];
        wo1 = (const float*)d_in[8];  bo1 = (const float*)d_in[9];
        wq2 = (const float*)d_in[10]; bq2 = (const float*)d_in[11];
        wk2 = (const float*)d_in[12]; bk2 = (const float*)d_in[13];
        wv2 = (const float*)d_in[14]; bv2 = (const float*)d_in[15];
        wo2 = (const float*)d_in[16]; bo2 = (const float*)d_in[17];
    } else {
        wq1 = (const float*)d_in[2];  wk1 = (const float*)d_in[3];
        wv1 = (const float*)d_in[4];  wo1 = (const float*)d_in[5];
        bq1 = (const float*)d_in[6];  bk1 = (const float*)d_in[7];
        bv1 = (const float*)d_in[8];  bo1 = (const float*)d_in[9];
        wq2 = (const float*)d_in[10]; wk2 = (const float*)d_in[11];
        wv2 = (const float*)d_in[12]; wo2 = (const float*)d_in[13];
        bq2 = (const float*)d_in[14]; bk2 = (const float*)d_in[15];
        bv2 = (const float*)d_in[16]; bo2 = (const float*)d_in[17];
    }
    wff1 = (const float*)d_in[18]; bff1 = (const float*)d_in[19];
    wff2 = (const float*)d_in[20]; bff2 = (const float*)d_in[21];
    g1 = (const float*)d_in[22]; be1 = (const float*)d_in[23];
    g2 = (const float*)d_in[24]; be2 = (const float*)d_in[25];
    g3 = (const float*)d_in[26]; be3 = (const float*)d_in[27];

    float *t1, *o1, *o2;
    cudaGetSymbolAddress((void**)&t1, g_t1);
    cudaGetSymbolAddress((void**)&o1, g_o1);
    cudaGetSymbolAddress((void**)&o2, g_o2);

    uint16_t *x3, *enc3, *o13, *o23, *ctx3, *ff3, *q2, *k2, *v2;
    uint16_t *w3, *wf13, *wf23;
    cudaGetSymbolAddress((void**)&x3,   g_x3);
    cudaGetSymbolAddress((void**)&enc3, g_enc3);
    cudaGetSymbolAddress((void**)&o13,  g_o13);
    cudaGetSymbolAddress((void**)&o23,  g_o23);
    cudaGetSymbolAddress((void**)&ctx3, g_ctx3);
    cudaGetSymbolAddress((void**)&ff3,  g_ff3);
    cudaGetSymbolAddress((void**)&q2,   g_q2);
    cudaGetSymbolAddress((void**)&k2,   g_k2);
    cudaGetSymbolAddress((void**)&v2,   g_v2);
    cudaGetSymbolAddress((void**)&w3,   g_w3);
    cudaGetSymbolAddress((void**)&wf13, g_wf13);
    cudaGetSymbolAddress((void**)&wf23, g_wf23);

    cudaFuncSetAttribute(bf16s_gemm_kernel<false, 0>,
        cudaFuncAttributeMaxDynamicSharedMemorySize, GEMM_SMEM_BYTES);
    cudaFuncSetAttribute(bf16s_gemm_kernel<false, 2>,
        cudaFuncAttributeMaxDynamicSharedMemorySize, GEMM_SMEM_BYTES);
    cudaFuncSetAttribute(bf16s_gemm_kernel<true, 3>,
        cudaFuncAttributeMaxDynamicSharedMemorySize, GEMM_SMEM_BYTES);
    cudaFuncSetAttribute(attn_tc_kernel,
        cudaFuncAttributeMaxDynamicSharedMemorySize, ATT_SMEM);

    const dim3 gD(D / 128, BS / 128);
    const dim3 gF1(DFF / 128, BS / 128);
    const dim3 gAttn(64, 16);
    const int SM = GEMM_SMEM_BYTES;
    const size_t WSZ = (size_t)3 * D * D;

    // splits: 3 launches total (V-projection GEMM becomes launch #6 for ncu)
    W8 w8s;
    w8s.p[0] = wq1; w8s.p[1] = wk1; w8s.p[2] = wv1; w8s.p[3] = wo1;
    w8s.p[4] = wq2; w8s.p[5] = wk2; w8s.p[6] = wv2; w8s.p[7] = wo2;
    split_w8_kernel<<<8192, 256>>>(w8s, w3);
    split_wff_kernel<<<8192, 256>>>(wff1, wff2, wf13, wf23);
    split_xe_kernel<<<8192, 256>>>(x, enc, x3, enc3);

    // ---- self-attention block (causal) ----
    bf16s_gemm_kernel<false, 2><<<gD, 256, SM>>>(x3, w3 + 0 * WSZ, bq1, q2, BS, D, 3 * D);
    bf16s_gemm_kernel<false, 2><<<gD, 256, SM>>>(x3, w3 + 1 * WSZ, bk1, k2, BS, D, 3 * D);
    bf16s_gemm_kernel<false, 2><<<gD, 256, SM>>>(x3, w3 + 2 * WSZ, bv1, v2, BS, D, 3 * D);
    attn_tc_kernel<<<gAttn, 128, ATT_SMEM>>>(q2, k2, v2, ctx3, 1);
    bf16s_gemm_kernel<false, 0><<<gD, 256, SM>>>(ctx3, w3 + 3 * WSZ, bo1, t1, BS, D, 3 * D);
    ln_kernel<<<BS, 256>>>(x, t1, g1, be1, o1, o13);

    // ---- cross-attention block ----
    bf16s_gemm_kernel<false, 2><<<gD, 256, SM>>>(o13,  w3 + 4 * WSZ, bq2, q2, BS, D, 3 * D);
    bf16s_gemm_kernel<false, 2><<<gD, 256, SM>>>(enc3, w3 + 5 * WSZ, bk2, k2, BS, D, 3 * D);
    bf16s_gemm_kernel<false, 2><<<gD, 256, SM>>>(enc3, w3 + 6 * WSZ, bv2, v2, BS, D, 3 * D);
    attn_tc_kernel<<<gAttn, 128, ATT_SMEM>>>(q2, k2, v2, ctx3, 0);
    bf16s_gemm_kernel<false, 0><<<gD, 256, SM>>>(ctx3, w3 + 7 * WSZ, bo2, t1, BS, D, 3 * D);
    ln_kernel<<<BS, 256>>>(o1, t1, g2, be2, o2, o23);

    // ---- FFN block ----
    bf16s_gemm_kernel<true, 3><<<gF1, 256, SM>>>(o23, wf13, bff1, ff3, BS, DFF, 3 * D);
    bf16s_gemm_kernel<false, 0><<<gD, 256, SM>>>(ff3, wf23, bff2, t1, BS, D, 3 * DFF);
    ln_kernel<<<BS, 256>>>(o2, t1, g3, be3, (float*)d_out, nullptr);

    (void)n_in; (void)out_size;
}